// round 7
// baseline (speedup 1.0000x reference)
#include <cuda_runtime.h>
#include <cstdint>

#define NMAX 100000
#define EMAX 1600000
#define D 128

// ---- scratch (no allocations allowed -> __device__ globals) ----
__device__ int   g_deg[NMAX];
__device__ float g_dinv[NMAX];
__device__ int   g_colptr[NMAX + 1];
__device__ int   g_cursor[NMAX];
__device__ int   g_srow[EMAX];
__device__ float g_h[(size_t)NMAX * D];
__device__ float g_z[(size_t)NMAX * D];
__device__ int   g_part[256];

__device__ __forceinline__ float to_tf32(float x) {
    float y;
    asm("cvt.rna.tf32.f32 %0, %1;" : "=f"(y) : "f"(x));
    return y;
}

// ---------------- degree ----------------
__global__ void k_deg_init(int n) {
    int i = blockIdx.x * blockDim.x + threadIdx.x;
    if (i < n) g_deg[i] = 0;
}
__global__ void k_deg_count(const int* __restrict__ col, int e) {
    int i = blockIdx.x * blockDim.x + threadIdx.x;
    if (i < e) atomicAdd(&g_deg[col[i]], 1);
}

// ---------------- exclusive scan of g_deg -> g_colptr (+dinv fused) ----------------
#define SCAN_T 256
#define SCAN_I 8
#define SCAN_C (SCAN_T * SCAN_I)

__global__ void k_scan_partial(int n) {
    __shared__ int ss[SCAN_T];
    int b = blockIdx.x, tid = threadIdx.x;
    int base = b * SCAN_C + tid * SCAN_I;
    int s = 0;
    #pragma unroll
    for (int i = 0; i < SCAN_I; i++) {
        int idx = base + i;
        if (idx < n) s += g_deg[idx];
    }
    ss[tid] = s;
    __syncthreads();
    for (int off = SCAN_T / 2; off > 0; off >>= 1) {
        if (tid < off) ss[tid] += ss[tid + off];
        __syncthreads();
    }
    if (tid == 0) g_part[b] = ss[0];
}

// warp-parallel exclusive scan of up to 64 partials (1 warp, 2 elems/lane)
__global__ void k_scan_offsets(int nb) {
    int lane = threadIdx.x;
    int a = (lane < nb) ? g_part[lane] : 0;
    int b = (lane + 32 < nb) ? g_part[lane + 32] : 0;
    int sa = a, sb = b;
    #pragma unroll
    for (int off = 1; off < 32; off <<= 1) {
        int ta = __shfl_up_sync(0xFFFFFFFF, sa, off);
        int tb = __shfl_up_sync(0xFFFFFFFF, sb, off);
        if (lane >= off) { sa += ta; sb += tb; }
    }
    int totA = __shfl_sync(0xFFFFFFFF, sa, 31);
    if (lane < nb) g_part[lane] = sa - a;
    if (lane + 32 < nb) g_part[lane + 32] = totA + sb - b;
}

__global__ void k_scan_final(int n, int e) {
    __shared__ int ss[SCAN_T];
    int b = blockIdx.x, tid = threadIdx.x;
    int base = b * SCAN_C + tid * SCAN_I;
    int vals[SCAN_I];
    int degs[SCAN_I];
    int local = 0;
    #pragma unroll
    for (int i = 0; i < SCAN_I; i++) {
        int idx = base + i;
        int v = (idx < n) ? g_deg[idx] : 0;
        degs[i] = v;
        vals[i] = local;
        local += v;
    }
    ss[tid] = local;
    __syncthreads();
    for (int off = 1; off < SCAN_T; off <<= 1) {
        int v = 0;
        if (tid >= off) v = ss[tid - off];
        __syncthreads();
        ss[tid] += v;
        __syncthreads();
    }
    int toff = g_part[b] + ss[tid] - local;
    #pragma unroll
    for (int i = 0; i < SCAN_I; i++) {
        int idx = base + i;
        if (idx < n) {
            int p = toff + vals[i];
            g_colptr[idx] = p;
            g_cursor[idx] = p;
            g_dinv[idx] = rsqrtf((float)(degs[i] + 1));
        }
    }
    if (b == 0 && tid == 0) g_colptr[n] = e;
}

// ---------------- CSR fill ----------------
__global__ void k_fill(const int* __restrict__ row, const int* __restrict__ col, int e) {
    int i = blockIdx.x * blockDim.x + threadIdx.x;
    if (i < e) {
        int p = atomicAdd(&g_cursor[col[i]], 1);
        g_srow[p] = row[i];
    }
}

#define MMA_TF32(d, a, b) \
    asm volatile("mma.sync.aligned.m16n8k8.row.col.f32.tf32.tf32.f32 " \
        "{%0,%1,%2,%3}, {%4,%5,%6,%7}, {%8,%9}, {%0,%1,%2,%3};" \
        : "+f"((d)[0]), "+f"((d)[1]), "+f"((d)[2]), "+f"((d)[3]) \
        : "r"((a)[0]), "r"((a)[1]), "r"((a)[2]), "r"((a)[3]), \
          "r"((b)[0]), "r"((b)[1]))

// ---------------- standalone tf32 GEMM (layer 1): 2 CTAs/SM, split-K smem ----------------
#define AST 68
#define BST 136
#define GSMEM_FLOATS (128 * AST + 64 * BST)   // 69632 B

__global__ void __launch_bounds__(256) k_gemm_mma(const float* __restrict__ A,
                                                  const float* __restrict__ W,
                                                  float* __restrict__ C, int n) {
    extern __shared__ float smem[];
    float* As = smem;
    float* Bs = smem + 128 * AST;

    int tid = threadIdx.x;
    int wid = tid >> 5, lane = tid & 31;
    int gq = lane >> 2;
    int cq = lane & 3;
    int row0 = blockIdx.x << 7;
    int wm = (wid >> 2) << 6;
    int wn = (wid & 3) << 5;

    float acc[4][4][4];
    #pragma unroll
    for (int mt = 0; mt < 4; mt++)
        #pragma unroll
        for (int nt = 0; nt < 4; nt++)
            #pragma unroll
            for (int i = 0; i < 4; i++)
                acc[mt][nt][i] = 0.f;

    const uint32_t* Au = (const uint32_t*)As;
    const uint32_t* Bu = (const uint32_t*)Bs;

    for (int ch = 0; ch < 2; ch++) {
        int k0 = ch << 6;
        #pragma unroll
        for (int it = 0; it < 8; it++) {
            int t = tid + it * 256;
            int m = t >> 4, kq = t & 15;
            int gm = row0 + m;
            float4 v = make_float4(0.f, 0.f, 0.f, 0.f);
            if (gm < n) v = *(const float4*)(A + (size_t)gm * D + k0 + kq * 4);
            v.x = to_tf32(v.x); v.y = to_tf32(v.y);
            v.z = to_tf32(v.z); v.w = to_tf32(v.w);
            *(float4*)(As + m * AST + kq * 4) = v;
        }
        #pragma unroll
        for (int it = 0; it < 8; it++) {
            int t = tid + it * 256;
            int k = t >> 5, nq = t & 31;
            float4 v = *(const float4*)(W + (size_t)(k0 + k) * D + nq * 4);
            v.x = to_tf32(v.x); v.y = to_tf32(v.y);
            v.z = to_tf32(v.z); v.w = to_tf32(v.w);
            *(float4*)(Bs + k * BST + nq * 4) = v;
        }
        __syncthreads();

        #pragma unroll
        for (int kt = 0; kt < 8; kt++) {
            int kl = kt << 3;
            uint32_t a[4][4];
            uint32_t b[4][2];
            #pragma unroll
            for (int mt = 0; mt < 4; mt++) {
                const uint32_t* ap = Au + (wm + (mt << 4)) * AST + kl;
                a[mt][0] = ap[gq * AST + cq];
                a[mt][1] = ap[(gq + 8) * AST + cq];
                a[mt][2] = ap[gq * AST + cq + 4];
                a[mt][3] = ap[(gq + 8) * AST + cq + 4];
            }
            #pragma unroll
            for (int nt = 0; nt < 4; nt++) {
                const uint32_t* bp = Bu + kl * BST + wn + (nt << 3);
                b[nt][0] = bp[cq * BST + gq];
                b[nt][1] = bp[(cq + 4) * BST + gq];
            }
            #pragma unroll
            for (int mt = 0; mt < 4; mt++)
                #pragma unroll
                for (int nt = 0; nt < 4; nt++)
                    MMA_TF32(acc[mt][nt], a[mt], b[nt]);
        }
        __syncthreads();
    }

    #pragma unroll
    for (int mt = 0; mt < 4; mt++) {
        int r0 = row0 + wm + (mt << 4) + gq;
        int r1 = r0 + 8;
        #pragma unroll
        for (int nt = 0; nt < 4; nt++) {
            int cc = wn + (nt << 3) + (cq << 1);
            if (r0 < n)
                *(float2*)(C + (size_t)r0 * D + cc) =
                    make_float2(acc[mt][nt][0], acc[mt][nt][1]);
            if (r1 < n)
                *(float2*)(C + (size_t)r1 * D + cc) =
                    make_float2(acc[mt][nt][2], acc[mt][nt][3]);
        }
    }
}

// ---------------- FUSED: z = relu(Ahat h + b1) into smem, then C = z @ W2 ----------------
// As full-K [128][132] = 67584 B ; Bs [64][136] = 34816 B ; total 102400 B -> 2 CTA/SM
#define F_AST 132
#define F_BST 136
#define FSMEM_FLOATS (128 * F_AST + 64 * F_BST)

__global__ void __launch_bounds__(256) k_agg_gemm(const float* __restrict__ h,
                                                  const float* __restrict__ bias,
                                                  const float* __restrict__ W,
                                                  float* __restrict__ C, int n) {
    extern __shared__ float smem[];
    float* As = smem;
    float* Bs = smem + 128 * F_AST;

    int tid = threadIdx.x;
    int wid = tid >> 5, lane = tid & 31;
    int row0 = blockIdx.x << 7;

    // ---- phase 1: aggregate 16 nodes per warp into As (bias+relu+tf32) ----
    {
        const float4* h4 = (const float4*)h;
        float4 bv = ((const float4*)bias)[lane];
        #pragma unroll 1
        for (int nd = 0; nd < 16; nd++) {
            int l = wid * 16 + nd;        // local row
            int c = row0 + l;
            if (c >= n) break;
            float dc = g_dinv[c];
            float4 v = h4[(size_t)c * 32 + lane];
            float s = dc * dc;
            float ax = v.x * s, ay = v.y * s, az = v.z * s, aw = v.w * s;

            int i = g_colptr[c];
            int end = g_colptr[c + 1];
            // 2-deep pipeline: row i in u0/w0, row i+1 prefetching into u1/w1
            float4 u0, u1;
            float w0 = 0.f, w1 = 0.f;
            if (i < end) {
                int r = g_srow[i];
                w0 = g_dinv[r] * dc;
                u0 = h4[(size_t)r * 32 + lane];
            }
            if (i + 1 < end) {
                int r = g_srow[i + 1];
                w1 = g_dinv[r] * dc;
                u1 = h4[(size_t)r * 32 + lane];
            }
            for (; i < end; i++) {
                float4 u2; float w2 = 0.f;
                if (i + 2 < end) {
                    int r = g_srow[i + 2];
                    w2 = g_dinv[r] * dc;
                    u2 = h4[(size_t)r * 32 + lane];
                }
                ax += w0 * u0.x; ay += w0 * u0.y;
                az += w0 * u0.z; aw += w0 * u0.w;
                u0 = u1; w0 = w1;
                u1 = u2; w1 = w2;
            }
            ax = fmaxf(ax + bv.x, 0.f);
            ay = fmaxf(ay + bv.y, 0.f);
            az = fmaxf(az + bv.z, 0.f);
            aw = fmaxf(aw + bv.w, 0.f);
            float4 o = make_float4(to_tf32(ax), to_tf32(ay), to_tf32(az), to_tf32(aw));
            *(float4*)(As + l * F_AST + lane * 4) = o;
        }
    }
    __syncthreads();

    // ---- phase 2: C = As @ W (tf32 mma), Bs double-chunked ----
    int gq = lane >> 2;
    int cq = lane & 3;
    int wm = (wid >> 2) << 6;
    int wn = (wid & 3) << 5;

    float acc[4][4][4];
    #pragma unroll
    for (int mt = 0; mt < 4; mt++)
        #pragma unroll
        for (int nt = 0; nt < 4; nt++)
            #pragma unroll
            for (int i = 0; i < 4; i++)
                acc[mt][nt][i] = 0.f;

    const uint32_t* Au = (const uint32_t*)As;
    const uint32_t* Bu = (const uint32_t*)Bs;

    for (int ch = 0; ch < 2; ch++) {
        int k0 = ch << 6;
        #pragma unroll
        for (int it = 0; it < 8; it++) {
            int t = tid + it * 256;
            int k = t >> 5, nq = t & 31;
            float4 v = *(const float4*)(W + (size_t)(k0 + k) * D + nq * 4);
            v.x = to_tf32(v.x); v.y = to_tf32(v.y);
            v.z = to_tf32(v.z); v.w = to_tf32(v.w);
            *(float4*)(Bs + k * F_BST + nq * 4) = v;
        }
        __syncthreads();

        #pragma unroll
        for (int kt = 0; kt < 8; kt++) {
            int kl = k0 + (kt << 3);
            uint32_t a[4][4];
            uint32_t b[4][2];
            #pragma unroll
            for (int mt = 0; mt < 4; mt++) {
                const uint32_t* ap = Au + (wm + (mt << 4)) * F_AST + kl;
                a[mt][0] = ap[gq * F_AST + cq];
                a[mt][1] = ap[(gq + 8) * F_AST + cq];
                a[mt][2] = ap[gq * F_AST + cq + 4];
                a[mt][3] = ap[(gq + 8) * F_AST + cq + 4];
            }
            #pragma unroll
            for (int nt = 0; nt < 4; nt++) {
                const uint32_t* bp = Bu + (kt << 3) * F_BST + wn + (nt << 3);
                b[nt][0] = bp[cq * F_BST + gq];
                b[nt][1] = bp[(cq + 4) * F_BST + gq];
            }
            #pragma unroll
            for (int mt = 0; mt < 4; mt++)
                #pragma unroll
                for (int nt = 0; nt < 4; nt++)
                    MMA_TF32(acc[mt][nt], a[mt], b[nt]);
        }
        __syncthreads();
    }

    #pragma unroll
    for (int mt = 0; mt < 4; mt++) {
        int r0 = row0 + wm + (mt << 4) + gq;
        int r1 = r0 + 8;
        #pragma unroll
        for (int nt = 0; nt < 4; nt++) {
            int cc = wn + (nt << 3) + (cq << 1);
            if (r0 < n)
                *(float2*)(C + (size_t)r0 * D + cc) =
                    make_float2(acc[mt][nt][0], acc[mt][nt][1]);
            if (r1 < n)
                *(float2*)(C + (size_t)r1 * D + cc) =
                    make_float2(acc[mt][nt][2], acc[mt][nt][3]);
        }
    }
}

// ---------------- standalone aggregation (layer 2 output) ----------------
__global__ void k_agg(const float* __restrict__ h, const float* __restrict__ bias,
                      float* __restrict__ out, int n, int do_relu) {
    int gt = blockIdx.x * blockDim.x + threadIdx.x;
    int c = gt >> 5;
    int lane = gt & 31;
    if (c >= n) return;

    float dc = g_dinv[c];
    const float4* h4 = (const float4*)h;
    float4 v = h4[(size_t)c * 32 + lane];
    float s = dc * dc;
    float ax = v.x * s, ay = v.y * s, az = v.z * s, aw = v.w * s;

    int i = g_colptr[c];
    int end = g_colptr[c + 1];
    int r_next = (i < end) ? g_srow[i] : 0;
    while (i < end) {
        int r = r_next;
        int j = i + 1;
        if (j < end) r_next = g_srow[j];
        float w = g_dinv[r] * dc;
        float4 u = h4[(size_t)r * 32 + lane];
        ax += w * u.x;
        ay += w * u.y;
        az += w * u.z;
        aw += w * u.w;
        i = j;
    }

    float4 bv = ((const float4*)bias)[lane];
    ax += bv.x; ay += bv.y; az += bv.z; aw += bv.w;
    if (do_relu) {
        ax = fmaxf(ax, 0.f); ay = fmaxf(ay, 0.f);
        az = fmaxf(az, 0.f); aw = fmaxf(aw, 0.f);
    }
    ((float4*)out)[(size_t)c * 32 + lane] = make_float4(ax, ay, az, aw);
}

// ---------------- launch ----------------
extern "C" void kernel_launch(void* const* d_in, const int* in_sizes, int n_in,
                              void* d_out, int out_size) {
    const float* x  = (const float*)d_in[0];
    const int*   ei = (const int*)d_in[1];
    const float* W1 = (const float*)d_in[2];
    const float* b1 = (const float*)d_in[3];
    const float* W2 = (const float*)d_in[4];
    const float* b2 = (const float*)d_in[5];
    float* out = (float*)d_out;

    int n = in_sizes[0] / D;
    int e = in_sizes[1] / 2;
    const int* row = ei;
    const int* col = ei + e;

    void *ph = nullptr, *pz = nullptr;
    cudaGetSymbolAddress(&ph, g_h);
    cudaGetSymbolAddress(&pz, g_z);
    float* h = (float*)ph;
    float* z = (float*)pz;

    static int init_done = 0;
    static cudaStream_t s2 = nullptr;
    static cudaEvent_t ev_fork = nullptr, ev_join = nullptr;
    if (!init_done) {
        cudaFuncSetAttribute(k_gemm_mma, cudaFuncAttributeMaxDynamicSharedMemorySize,
                             GSMEM_FLOATS * 4);
        cudaFuncSetAttribute(k_agg_gemm, cudaFuncAttributeMaxDynamicSharedMemorySize,
                             FSMEM_FLOATS * 4);
        if (cudaStreamCreateWithFlags(&s2, cudaStreamNonBlocking) != cudaSuccess) s2 = nullptr;
        if (cudaEventCreateWithFlags(&ev_fork, cudaEventDisableTiming) != cudaSuccess) ev_fork = nullptr;
        if (cudaEventCreateWithFlags(&ev_join, cudaEventDisableTiming) != cudaSuccess) ev_join = nullptr;
        init_done = 1;
    }
    bool fork = (s2 && ev_fork && ev_join);
    cudaStream_t sc = fork ? s2 : (cudaStream_t)0;

    int nb = (n + SCAN_C - 1) / SCAN_C;
    int gemm_blocks = (n + 127) / 128;
    int agg_blocks = (n * 32 + 255) / 256;

    if (fork) {
        cudaEventRecord(ev_fork, 0);
        cudaStreamWaitEvent(s2, ev_fork, 0);
    }

    // ---- CSR build chain (side stream when forked) ----
    k_deg_init<<<(n + 255) / 256, 256, 0, sc>>>(n);
    k_deg_count<<<(e + 255) / 256, 256, 0, sc>>>(col, e);
    k_scan_partial<<<nb, SCAN_T, 0, sc>>>(n);
    k_scan_offsets<<<1, 32, 0, sc>>>(nb);
    k_scan_final<<<nb, SCAN_T, 0, sc>>>(n, e);
    k_fill<<<(e + 255) / 256, 256, 0, sc>>>(row, col, e);

    if (fork) cudaEventRecord(ev_join, s2);

    // ---- GEMM1 overlaps the CSR build ----
    k_gemm_mma<<<gemm_blocks, 256, GSMEM_FLOATS * 4>>>(x, W1, h, n);

    if (fork) cudaStreamWaitEvent((cudaStream_t)0, ev_join, 0);

    // fused: z_smem = relu(Ahat h + b1) ; g_z = z_smem @ W2
    k_agg_gemm<<<gemm_blocks, 256, FSMEM_FLOATS * 4>>>(h, b1, W2, z, n);
    // final aggregate: out = Ahat z + b2
    k_agg<<<agg_blocks, 256>>>(z, b2, out, n, 0);
}

// round 9
// speedup vs baseline: 1.5067x; 1.5067x over previous
#include <cuda_runtime.h>
#include <cstdint>

#define NMAX 100000
#define EMAX 1600000
#define D 128

// ---- scratch (no allocations allowed -> __device__ globals) ----
__device__ int   g_deg[NMAX];
__device__ float g_dinv[NMAX];
__device__ int   g_colptr[NMAX + 1];
__device__ int   g_cursor[NMAX];
__device__ int   g_srow[EMAX];
__device__ float g_h[(size_t)NMAX * D];
__device__ float g_z[(size_t)NMAX * D];
__device__ int   g_part[256];

__device__ __forceinline__ float to_tf32(float x) {
    float y;
    asm("cvt.rna.tf32.f32 %0, %1;" : "=f"(y) : "f"(x));
    return y;
}

// ---------------- degree ----------------
__global__ void k_deg_init(int n) {
    int i = blockIdx.x * blockDim.x + threadIdx.x;
    if (i < n) g_deg[i] = 0;
}
__global__ void k_deg_count(const int* __restrict__ col, int e) {
    int i = blockIdx.x * blockDim.x + threadIdx.x;
    if (i < e) atomicAdd(&g_deg[col[i]], 1);
}

// ---------------- exclusive scan of g_deg -> g_colptr (+dinv fused) ----------------
#define SCAN_T 256
#define SCAN_I 8
#define SCAN_C (SCAN_T * SCAN_I)

__global__ void k_scan_partial(int n) {
    __shared__ int ss[SCAN_T];
    int b = blockIdx.x, tid = threadIdx.x;
    int base = b * SCAN_C + tid * SCAN_I;
    int s = 0;
    #pragma unroll
    for (int i = 0; i < SCAN_I; i++) {
        int idx = base + i;
        if (idx < n) s += g_deg[idx];
    }
    ss[tid] = s;
    __syncthreads();
    for (int off = SCAN_T / 2; off > 0; off >>= 1) {
        if (tid < off) ss[tid] += ss[tid + off];
        __syncthreads();
    }
    if (tid == 0) g_part[b] = ss[0];
}

// warp-parallel exclusive scan of up to 64 partials
__global__ void k_scan_offsets(int nb) {
    int lane = threadIdx.x;
    int a = (lane < nb) ? g_part[lane] : 0;
    int b = (lane + 32 < nb) ? g_part[lane + 32] : 0;
    int sa = a, sb = b;
    #pragma unroll
    for (int off = 1; off < 32; off <<= 1) {
        int ta = __shfl_up_sync(0xFFFFFFFF, sa, off);
        int tb = __shfl_up_sync(0xFFFFFFFF, sb, off);
        if (lane >= off) { sa += ta; sb += tb; }
    }
    int totA = __shfl_sync(0xFFFFFFFF, sa, 31);
    if (lane < nb) g_part[lane] = sa - a;
    if (lane + 32 < nb) g_part[lane + 32] = totA + sb - b;
}

__global__ void k_scan_final(int n, int e) {
    __shared__ int ss[SCAN_T];
    int b = blockIdx.x, tid = threadIdx.x;
    int base = b * SCAN_C + tid * SCAN_I;
    int vals[SCAN_I];
    int degs[SCAN_I];
    int local = 0;
    #pragma unroll
    for (int i = 0; i < SCAN_I; i++) {
        int idx = base + i;
        int v = (idx < n) ? g_deg[idx] : 0;
        degs[i] = v;
        vals[i] = local;
        local += v;
    }
    ss[tid] = local;
    __syncthreads();
    for (int off = 1; off < SCAN_T; off <<= 1) {
        int v = 0;
        if (tid >= off) v = ss[tid - off];
        __syncthreads();
        ss[tid] += v;
        __syncthreads();
    }
    int toff = g_part[b] + ss[tid] - local;
    #pragma unroll
    for (int i = 0; i < SCAN_I; i++) {
        int idx = base + i;
        if (idx < n) {
            int p = toff + vals[i];
            g_colptr[idx] = p;
            g_cursor[idx] = p;
            g_dinv[idx] = rsqrtf((float)(degs[i] + 1));
        }
    }
    if (b == 0 && tid == 0) g_colptr[n] = e;
}

// ---------------- CSR fill ----------------
__global__ void k_fill(const int* __restrict__ row, const int* __restrict__ col, int e) {
    int i = blockIdx.x * blockDim.x + threadIdx.x;
    if (i < e) {
        int p = atomicAdd(&g_cursor[col[i]], 1);
        g_srow[p] = row[i];
    }
}

// ---------------- tf32 mma.sync GEMM: C[n,128] = A[n,128] @ W[128,128] ----------------
// CTA tile 128x128, K split into 2 chunks of 64 -> 70KB smem -> 2 CTAs/SM.
#define AST 68
#define BST 136
#define GSMEM_FLOATS (128 * AST + 64 * BST)   // 69632 B

#define MMA_TF32(d, a, b) \
    asm volatile("mma.sync.aligned.m16n8k8.row.col.f32.tf32.tf32.f32 " \
        "{%0,%1,%2,%3}, {%4,%5,%6,%7}, {%8,%9}, {%0,%1,%2,%3};" \
        : "+f"((d)[0]), "+f"((d)[1]), "+f"((d)[2]), "+f"((d)[3]) \
        : "r"((a)[0]), "r"((a)[1]), "r"((a)[2]), "r"((a)[3]), \
          "r"((b)[0]), "r"((b)[1]))

__global__ void __launch_bounds__(256) k_gemm_mma(const float* __restrict__ A,
                                                  const float* __restrict__ W,
                                                  float* __restrict__ C, int n) {
    extern __shared__ float smem[];
    float* As = smem;
    float* Bs = smem + 128 * AST;

    int tid = threadIdx.x;
    int wid = tid >> 5, lane = tid & 31;
    int gq = lane >> 2;
    int cq = lane & 3;
    int row0 = blockIdx.x << 7;
    int wm = (wid >> 2) << 6;
    int wn = (wid & 3) << 5;

    float acc[4][4][4];
    #pragma unroll
    for (int mt = 0; mt < 4; mt++)
        #pragma unroll
        for (int nt = 0; nt < 4; nt++)
            #pragma unroll
            for (int i = 0; i < 4; i++)
                acc[mt][nt][i] = 0.f;

    const uint32_t* Au = (const uint32_t*)As;
    const uint32_t* Bu = (const uint32_t*)Bs;

    for (int ch = 0; ch < 2; ch++) {
        int k0 = ch << 6;
        #pragma unroll
        for (int it = 0; it < 8; it++) {
            int t = tid + it * 256;
            int m = t >> 4, kq = t & 15;
            int gm = row0 + m;
            float4 v = make_float4(0.f, 0.f, 0.f, 0.f);
            if (gm < n) v = *(const float4*)(A + (size_t)gm * D + k0 + kq * 4);
            v.x = to_tf32(v.x); v.y = to_tf32(v.y);
            v.z = to_tf32(v.z); v.w = to_tf32(v.w);
            *(float4*)(As + m * AST + kq * 4) = v;
        }
        #pragma unroll
        for (int it = 0; it < 8; it++) {
            int t = tid + it * 256;
            int k = t >> 5, nq = t & 31;
            float4 v = *(const float4*)(W + (size_t)(k0 + k) * D + nq * 4);
            v.x = to_tf32(v.x); v.y = to_tf32(v.y);
            v.z = to_tf32(v.z); v.w = to_tf32(v.w);
            *(float4*)(Bs + k * BST + nq * 4) = v;
        }
        __syncthreads();

        #pragma unroll
        for (int kt = 0; kt < 8; kt++) {
            int kl = kt << 3;
            uint32_t a[4][4];
            uint32_t b[4][2];
            #pragma unroll
            for (int mt = 0; mt < 4; mt++) {
                const uint32_t* ap = Au + (wm + (mt << 4)) * AST + kl;
                a[mt][0] = ap[gq * AST + cq];
                a[mt][1] = ap[(gq + 8) * AST + cq];
                a[mt][2] = ap[gq * AST + cq + 4];
                a[mt][3] = ap[(gq + 8) * AST + cq + 4];
            }
            #pragma unroll
            for (int nt = 0; nt < 4; nt++) {
                const uint32_t* bp = Bu + kl * BST + wn + (nt << 3);
                b[nt][0] = bp[cq * BST + gq];
                b[nt][1] = bp[(cq + 4) * BST + gq];
            }
            #pragma unroll
            for (int mt = 0; mt < 4; mt++)
                #pragma unroll
                for (int nt = 0; nt < 4; nt++)
                    MMA_TF32(acc[mt][nt], a[mt], b[nt]);
        }
        __syncthreads();
    }

    #pragma unroll
    for (int mt = 0; mt < 4; mt++) {
        int r0 = row0 + wm + (mt << 4) + gq;
        int r1 = r0 + 8;
        #pragma unroll
        for (int nt = 0; nt < 4; nt++) {
            int cc = wn + (nt << 3) + (cq << 1);
            if (r0 < n)
                *(float2*)(C + (size_t)r0 * D + cc) =
                    make_float2(acc[mt][nt][0], acc[mt][nt][1]);
            if (r1 < n)
                *(float2*)(C + (size_t)r1 * D + cc) =
                    make_float2(acc[mt][nt][2], acc[mt][nt][3]);
        }
    }
}

// ---------------- aggregation over node range [c0, c1) ----------------
// one warp per node; 2 full rows (index+data) in flight to hide L2 latency
__global__ void k_agg(const float* __restrict__ h, const float* __restrict__ bias,
                      float* __restrict__ out, int c0, int c1, int do_relu) {
    int gt = blockIdx.x * blockDim.x + threadIdx.x;
    int c = c0 + (gt >> 5);
    int lane = gt & 31;
    if (c >= c1) return;

    float dc = g_dinv[c];
    const float4* h4 = (const float4*)h;
    float4 v = h4[(size_t)c * 32 + lane];
    float s = dc * dc;
    float ax = v.x * s, ay = v.y * s, az = v.z * s, aw = v.w * s;

    int i = g_colptr[c];
    int end = g_colptr[c + 1];
    float4 u0 = make_float4(0.f, 0.f, 0.f, 0.f);
    float4 u1 = make_float4(0.f, 0.f, 0.f, 0.f);
    float w0 = 0.f, w1 = 0.f;
    if (i < end) {
        int r = g_srow[i];
        w0 = g_dinv[r] * dc;
        u0 = h4[(size_t)r * 32 + lane];
    }
    if (i + 1 < end) {
        int r = g_srow[i + 1];
        w1 = g_dinv[r] * dc;
        u1 = h4[(size_t)r * 32 + lane];
    }
    for (; i < end; i++) {
        float4 u2 = make_float4(0.f, 0.f, 0.f, 0.f);
        float w2 = 0.f;
        if (i + 2 < end) {
            int r = g_srow[i + 2];
            w2 = g_dinv[r] * dc;
            u2 = h4[(size_t)r * 32 + lane];
        }
        ax += w0 * u0.x; ay += w0 * u0.y;
        az += w0 * u0.z; aw += w0 * u0.w;
        u0 = u1; w0 = w1;
        u1 = u2; w1 = w2;
    }

    float4 bv = ((const float4*)bias)[lane];
    ax += bv.x; ay += bv.y; az += bv.z; aw += bv.w;
    if (do_relu) {
        ax = fmaxf(ax, 0.f); ay = fmaxf(ay, 0.f);
        az = fmaxf(az, 0.f); aw = fmaxf(aw, 0.f);
    }
    ((float4*)out)[(size_t)c * 32 + lane] = make_float4(ax, ay, az, aw);
}

// ---------------- launch ----------------
extern "C" void kernel_launch(void* const* d_in, const int* in_sizes, int n_in,
                              void* d_out, int out_size) {
    const float* x  = (const float*)d_in[0];
    const int*   ei = (const int*)d_in[1];
    const float* W1 = (const float*)d_in[2];
    const float* b1 = (const float*)d_in[3];
    const float* W2 = (const float*)d_in[4];
    const float* b2 = (const float*)d_in[5];
    float* out = (float*)d_out;

    int n = in_sizes[0] / D;
    int e = in_sizes[1] / 2;
    const int* row = ei;
    const int* col = ei + e;

    void *ph = nullptr, *pz = nullptr;
    cudaGetSymbolAddress(&ph, g_h);
    cudaGetSymbolAddress(&pz, g_z);
    float* h = (float*)ph;
    float* z = (float*)pz;

    static int init_done = 0;
    static cudaStream_t s2 = nullptr;
    static cudaEvent_t ev_fork = nullptr, ev_join = nullptr, ev_a0 = nullptr, ev_g0 = nullptr;
    if (!init_done) {
        cudaFuncSetAttribute(k_gemm_mma, cudaFuncAttributeMaxDynamicSharedMemorySize,
                             GSMEM_FLOATS * 4);
        if (cudaStreamCreateWithFlags(&s2, cudaStreamNonBlocking) != cudaSuccess) s2 = nullptr;
        if (cudaEventCreateWithFlags(&ev_fork, cudaEventDisableTiming) != cudaSuccess) ev_fork = nullptr;
        if (cudaEventCreateWithFlags(&ev_join, cudaEventDisableTiming) != cudaSuccess) ev_join = nullptr;
        if (cudaEventCreateWithFlags(&ev_a0, cudaEventDisableTiming) != cudaSuccess) ev_a0 = nullptr;
        if (cudaEventCreateWithFlags(&ev_g0, cudaEventDisableTiming) != cudaSuccess) ev_g0 = nullptr;
        init_done = 1;
    }
    bool fork = (s2 && ev_fork && ev_join && ev_a0 && ev_g0);
    cudaStream_t sc = fork ? s2 : (cudaStream_t)0;

    int nb = (n + SCAN_C - 1) / SCAN_C;
    int gemm_blocks = (n + 127) / 128;
    // split nodes at 128-aligned midpoint for the agg1/gemm2 pipeline
    int half_blocks = gemm_blocks / 2;
    int nh0 = half_blocks * 128;          // rows in chunk 0 (multiple of 128)
    if (nh0 <= 0 || nh0 >= n) { nh0 = n; half_blocks = gemm_blocks; }
    int nh1 = n - nh0;

    if (fork) {
        cudaEventRecord(ev_fork, 0);
        cudaStreamWaitEvent(s2, ev_fork, 0);
    }

    // ---- CSR build chain (side stream when forked) ----
    k_deg_init<<<(n + 255) / 256, 256, 0, sc>>>(n);
    k_deg_count<<<(e + 255) / 256, 256, 0, sc>>>(col, e);
    k_scan_partial<<<nb, SCAN_T, 0, sc>>>(n);
    k_scan_offsets<<<1, 32, 0, sc>>>(nb);
    k_scan_final<<<nb, SCAN_T, 0, sc>>>(n, e);
    k_fill<<<(e + 255) / 256, 256, 0, sc>>>(row, col, e);

    if (fork) cudaEventRecord(ev_join, s2);

    // ---- GEMM1 overlaps the CSR build ----
    k_gemm_mma<<<gemm_blocks, 256, GSMEM_FLOATS * 4>>>(x, W1, h, n);

    if (fork) cudaStreamWaitEvent((cudaStream_t)0, ev_join, 0);

    if (fork && nh1 > 0) {
        // pipelined: agg1(h0) -> [agg1(h1) || gemm2(h0)] -> gemm2(h1) -> agg2(all)
        k_agg<<<(nh0 * 32 + 255) / 256, 256>>>(h, b1, z, 0, nh0, 1);
        cudaEventRecord(ev_a0, 0);
        cudaStreamWaitEvent(s2, ev_a0, 0);
        k_gemm_mma<<<half_blocks, 256, GSMEM_FLOATS * 4, s2>>>(z, W2, h, nh0);
        cudaEventRecord(ev_g0, s2);

        k_agg<<<(nh1 * 32 + 255) / 256, 256>>>(h, b1, z, nh0, n, 1);
        k_gemm_mma<<<gemm_blocks - half_blocks, 256, GSMEM_FLOATS * 4>>>(
            z + (size_t)nh0 * D, W2, h + (size_t)nh0 * D, nh1);
        cudaStreamWaitEvent((cudaStream_t)0, ev_g0, 0);
        k_agg<<<(n * 32 + 255) / 256, 256>>>(h, b2, out, 0, n, 0);
    } else {
        k_agg<<<(n * 32 + 255) / 256, 256>>>(h, b1, z, 0, n, 1);
        k_gemm_mma<<<gemm_blocks, 256, GSMEM_FLOATS * 4>>>(z, W2, h, n);
        k_agg<<<(n * 32 + 255) / 256, 256>>>(h, b2, out, 0, n, 0);
    }
}

// round 10
// speedup vs baseline: 1.6297x; 1.0816x over previous
#include <cuda_runtime.h>
#include <cuda_fp16.h>
#include <cstdint>

#define NMAX 100000
#define EMAX 1600000
#define D 128

// ---- scratch (no allocations allowed -> __device__ globals) ----
__device__ int   g_deg[NMAX];
__device__ float g_dinv[NMAX];
__device__ int   g_colptr[NMAX + 1];
__device__ int   g_cursor[NMAX];
__device__ int   g_srow[EMAX];
__device__ uint2 g_hbuf[(size_t)NMAX * D / 4];   // fp16 features (8B-aligned rows)
__device__ uint2 g_zbuf[(size_t)NMAX * D / 4];
__device__ int   g_part[256];

__device__ __forceinline__ float to_tf32(float x) {
    float y;
    asm("cvt.rna.tf32.f32 %0, %1;" : "=f"(y) : "f"(x));
    return y;
}

// 4 halves (uint2) -> float4
__device__ __forceinline__ float4 h4f(uint2 u) {
    __half2 a = *reinterpret_cast<__half2*>(&u.x);
    __half2 b = *reinterpret_cast<__half2*>(&u.y);
    float2 fa = __half22float2(a), fb = __half22float2(b);
    return make_float4(fa.x, fa.y, fb.x, fb.y);
}

// ---------------- degree ----------------
__global__ void k_deg_init(int n) {
    int i = blockIdx.x * blockDim.x + threadIdx.x;
    if (i < n) g_deg[i] = 0;
}
__global__ void k_deg_count(const int* __restrict__ col, int e) {
    int i = blockIdx.x * blockDim.x + threadIdx.x;
    if (i < e) atomicAdd(&g_deg[col[i]], 1);
}

// ---------------- exclusive scan of g_deg -> g_colptr (+dinv fused) ----------------
#define SCAN_T 256
#define SCAN_I 8
#define SCAN_C (SCAN_T * SCAN_I)

__global__ void k_scan_partial(int n) {
    __shared__ int ss[SCAN_T];
    int b = blockIdx.x, tid = threadIdx.x;
    int base = b * SCAN_C + tid * SCAN_I;
    int s = 0;
    #pragma unroll
    for (int i = 0; i < SCAN_I; i++) {
        int idx = base + i;
        if (idx < n) s += g_deg[idx];
    }
    ss[tid] = s;
    __syncthreads();
    for (int off = SCAN_T / 2; off > 0; off >>= 1) {
        if (tid < off) ss[tid] += ss[tid + off];
        __syncthreads();
    }
    if (tid == 0) g_part[b] = ss[0];
}

__global__ void k_scan_offsets(int nb) {
    int lane = threadIdx.x;
    int a = (lane < nb) ? g_part[lane] : 0;
    int b = (lane + 32 < nb) ? g_part[lane + 32] : 0;
    int sa = a, sb = b;
    #pragma unroll
    for (int off = 1; off < 32; off <<= 1) {
        int ta = __shfl_up_sync(0xFFFFFFFF, sa, off);
        int tb = __shfl_up_sync(0xFFFFFFFF, sb, off);
        if (lane >= off) { sa += ta; sb += tb; }
    }
    int totA = __shfl_sync(0xFFFFFFFF, sa, 31);
    if (lane < nb) g_part[lane] = sa - a;
    if (lane + 32 < nb) g_part[lane + 32] = totA + sb - b;
}

__global__ void k_scan_final(int n, int e) {
    __shared__ int ss[SCAN_T];
    int b = blockIdx.x, tid = threadIdx.x;
    int base = b * SCAN_C + tid * SCAN_I;
    int vals[SCAN_I];
    int degs[SCAN_I];
    int local = 0;
    #pragma unroll
    for (int i = 0; i < SCAN_I; i++) {
        int idx = base + i;
        int v = (idx < n) ? g_deg[idx] : 0;
        degs[i] = v;
        vals[i] = local;
        local += v;
    }
    ss[tid] = local;
    __syncthreads();
    for (int off = 1; off < SCAN_T; off <<= 1) {
        int v = 0;
        if (tid >= off) v = ss[tid - off];
        __syncthreads();
        ss[tid] += v;
        __syncthreads();
    }
    int toff = g_part[b] + ss[tid] - local;
    #pragma unroll
    for (int i = 0; i < SCAN_I; i++) {
        int idx = base + i;
        if (idx < n) {
            int p = toff + vals[i];
            g_colptr[idx] = p;
            g_cursor[idx] = p;
            g_dinv[idx] = rsqrtf((float)(degs[i] + 1));
        }
    }
    if (b == 0 && tid == 0) g_colptr[n] = e;
}

// ---------------- CSR fill ----------------
__global__ void k_fill(const int* __restrict__ row, const int* __restrict__ col, int e) {
    int i = blockIdx.x * blockDim.x + threadIdx.x;
    if (i < e) {
        int p = atomicAdd(&g_cursor[col[i]], 1);
        g_srow[p] = row[i];
    }
}

// ---------------- tf32 mma.sync GEMM: C_fp16[n,128] = A[n,128] @ W[128,128] ----------------
#define AST 68
#define BST 136
#define GSMEM_FLOATS (128 * AST + 64 * BST)   // 69632 B

#define MMA_TF32(d, a, b) \
    asm volatile("mma.sync.aligned.m16n8k8.row.col.f32.tf32.tf32.f32 " \
        "{%0,%1,%2,%3}, {%4,%5,%6,%7}, {%8,%9}, {%0,%1,%2,%3};" \
        : "+f"((d)[0]), "+f"((d)[1]), "+f"((d)[2]), "+f"((d)[3]) \
        : "r"((a)[0]), "r"((a)[1]), "r"((a)[2]), "r"((a)[3]), \
          "r"((b)[0]), "r"((b)[1]))

__device__ __forceinline__ float4 load4(const float* p) { return *(const float4*)p; }
__device__ __forceinline__ float4 load4(const __half* p) {
    return h4f(*(const uint2*)p);
}

template <typename AT>
__global__ void __launch_bounds__(256) k_gemm_mma(const AT* __restrict__ A,
                                                  const float* __restrict__ W,
                                                  __half* __restrict__ C, int n) {
    extern __shared__ float smem[];
    float* As = smem;
    float* Bs = smem + 128 * AST;

    int tid = threadIdx.x;
    int wid = tid >> 5, lane = tid & 31;
    int gq = lane >> 2;
    int cq = lane & 3;
    int row0 = blockIdx.x << 7;
    int wm = (wid >> 2) << 6;
    int wn = (wid & 3) << 5;

    float acc[4][4][4];
    #pragma unroll
    for (int mt = 0; mt < 4; mt++)
        #pragma unroll
        for (int nt = 0; nt < 4; nt++)
            #pragma unroll
            for (int i = 0; i < 4; i++)
                acc[mt][nt][i] = 0.f;

    const uint32_t* Au = (const uint32_t*)As;
    const uint32_t* Bu = (const uint32_t*)Bs;

    for (int ch = 0; ch < 2; ch++) {
        int k0 = ch << 6;
        #pragma unroll
        for (int it = 0; it < 8; it++) {
            int t = tid + it * 256;
            int m = t >> 4, kq = t & 15;
            int gm = row0 + m;
            float4 v = make_float4(0.f, 0.f, 0.f, 0.f);
            if (gm < n) v = load4(A + (size_t)gm * D + k0 + kq * 4);
            v.x = to_tf32(v.x); v.y = to_tf32(v.y);
            v.z = to_tf32(v.z); v.w = to_tf32(v.w);
            *(float4*)(As + m * AST + kq * 4) = v;
        }
        #pragma unroll
        for (int it = 0; it < 8; it++) {
            int t = tid + it * 256;
            int k = t >> 5, nq = t & 31;
            float4 v = *(const float4*)(W + (size_t)(k0 + k) * D + nq * 4);
            v.x = to_tf32(v.x); v.y = to_tf32(v.y);
            v.z = to_tf32(v.z); v.w = to_tf32(v.w);
            *(float4*)(Bs + k * BST + nq * 4) = v;
        }
        __syncthreads();

        #pragma unroll
        for (int kt = 0; kt < 8; kt++) {
            int kl = kt << 3;
            uint32_t a[4][4];
            uint32_t b[4][2];
            #pragma unroll
            for (int mt = 0; mt < 4; mt++) {
                const uint32_t* ap = Au + (wm + (mt << 4)) * AST + kl;
                a[mt][0] = ap[gq * AST + cq];
                a[mt][1] = ap[(gq + 8) * AST + cq];
                a[mt][2] = ap[gq * AST + cq + 4];
                a[mt][3] = ap[(gq + 8) * AST + cq + 4];
            }
            #pragma unroll
            for (int nt = 0; nt < 4; nt++) {
                const uint32_t* bp = Bu + kl * BST + wn + (nt << 3);
                b[nt][0] = bp[cq * BST + gq];
                b[nt][1] = bp[(cq + 4) * BST + gq];
            }
            #pragma unroll
            for (int mt = 0; mt < 4; mt++)
                #pragma unroll
                for (int nt = 0; nt < 4; nt++)
                    MMA_TF32(acc[mt][nt], a[mt], b[nt]);
        }
        __syncthreads();
    }

    #pragma unroll
    for (int mt = 0; mt < 4; mt++) {
        int r0 = row0 + wm + (mt << 4) + gq;
        int r1 = r0 + 8;
        #pragma unroll
        for (int nt = 0; nt < 4; nt++) {
            int cc = wn + (nt << 3) + (cq << 1);
            if (r0 < n)
                *(__half2*)(C + (size_t)r0 * D + cc) =
                    __floats2half2_rn(acc[mt][nt][0], acc[mt][nt][1]);
            if (r1 < n)
                *(__half2*)(C + (size_t)r1 * D + cc) =
                    __floats2half2_rn(acc[mt][nt][2], acc[mt][nt][3]);
        }
    }
}

// ---------------- aggregation (fp16 gather, fp32 accumulate) ----------------
__device__ __forceinline__ void store4(float* p, float a, float b, float c, float d) {
    *(float4*)p = make_float4(a, b, c, d);
}
__device__ __forceinline__ void store4(__half* p, float a, float b, float c, float d) {
    *(__half2*)p = __floats2half2_rn(a, b);
    *(__half2*)(p + 2) = __floats2half2_rn(c, d);
}

template <typename OT>
__global__ void k_agg(const __half* __restrict__ h, const float* __restrict__ bias,
                      OT* __restrict__ out, int n, int do_relu) {
    int gt = blockIdx.x * blockDim.x + threadIdx.x;
    int c = gt >> 5;
    int lane = gt & 31;
    if (c >= n) return;

    float dc = g_dinv[c];
    const uint2* h4 = (const uint2*)h;   // 4 halves per lane
    float4 v = h4f(h4[(size_t)c * 32 + lane]);
    float s = dc * dc;
    float ax = v.x * s, ay = v.y * s, az = v.z * s, aw = v.w * s;

    int i = g_colptr[c];
    int end = g_colptr[c + 1];
    uint2 u0 = make_uint2(0, 0), u1 = make_uint2(0, 0);
    float w0 = 0.f, w1 = 0.f;
    if (i < end) {
        int r = g_srow[i];
        w0 = g_dinv[r] * dc;
        u0 = h4[(size_t)r * 32 + lane];
    }
    if (i + 1 < end) {
        int r = g_srow[i + 1];
        w1 = g_dinv[r] * dc;
        u1 = h4[(size_t)r * 32 + lane];
    }
    for (; i < end; i++) {
        uint2 u2 = make_uint2(0, 0);
        float w2 = 0.f;
        if (i + 2 < end) {
            int r = g_srow[i + 2];
            w2 = g_dinv[r] * dc;
            u2 = h4[(size_t)r * 32 + lane];
        }
        float4 f = h4f(u0);
        ax += w0 * f.x; ay += w0 * f.y;
        az += w0 * f.z; aw += w0 * f.w;
        u0 = u1; w0 = w1;
        u1 = u2; w1 = w2;
    }

    float4 bv = ((const float4*)bias)[lane];
    ax += bv.x; ay += bv.y; az += bv.z; aw += bv.w;
    if (do_relu) {
        ax = fmaxf(ax, 0.f); ay = fmaxf(ay, 0.f);
        az = fmaxf(az, 0.f); aw = fmaxf(aw, 0.f);
    }
    store4(out + (size_t)c * D + lane * 4, ax, ay, az, aw);
}

// ---------------- launch ----------------
extern "C" void kernel_launch(void* const* d_in, const int* in_sizes, int n_in,
                              void* d_out, int out_size) {
    const float* x  = (const float*)d_in[0];
    const int*   ei = (const int*)d_in[1];
    const float* W1 = (const float*)d_in[2];
    const float* b1 = (const float*)d_in[3];
    const float* W2 = (const float*)d_in[4];
    const float* b2 = (const float*)d_in[5];
    float* out = (float*)d_out;

    int n = in_sizes[0] / D;
    int e = in_sizes[1] / 2;
    const int* row = ei;
    const int* col = ei + e;

    void *ph = nullptr, *pz = nullptr;
    cudaGetSymbolAddress(&ph, g_hbuf);
    cudaGetSymbolAddress(&pz, g_zbuf);
    __half* h = (__half*)ph;
    __half* z = (__half*)pz;

    static int init_done = 0;
    static cudaStream_t s2 = nullptr;
    static cudaEvent_t ev_fork = nullptr, ev_join = nullptr;
    if (!init_done) {
        cudaFuncSetAttribute(k_gemm_mma<float>, cudaFuncAttributeMaxDynamicSharedMemorySize,
                             GSMEM_FLOATS * 4);
        cudaFuncSetAttribute(k_gemm_mma<__half>, cudaFuncAttributeMaxDynamicSharedMemorySize,
                             GSMEM_FLOATS * 4);
        if (cudaStreamCreateWithFlags(&s2, cudaStreamNonBlocking) != cudaSuccess) s2 = nullptr;
        if (cudaEventCreateWithFlags(&ev_fork, cudaEventDisableTiming) != cudaSuccess) ev_fork = nullptr;
        if (cudaEventCreateWithFlags(&ev_join, cudaEventDisableTiming) != cudaSuccess) ev_join = nullptr;
        init_done = 1;
    }
    bool fork = (s2 && ev_fork && ev_join);
    cudaStream_t sc = fork ? s2 : (cudaStream_t)0;

    int nb = (n + SCAN_C - 1) / SCAN_C;
    int gemm_blocks = (n + 127) / 128;
    int agg_blocks = (n * 32 + 255) / 256;

    if (fork) {
        cudaEventRecord(ev_fork, 0);
        cudaStreamWaitEvent(s2, ev_fork, 0);
    }

    // ---- CSR build chain (side stream when forked) ----
    k_deg_init<<<(n + 255) / 256, 256, 0, sc>>>(n);
    k_deg_count<<<(e + 255) / 256, 256, 0, sc>>>(col, e);
    k_scan_partial<<<nb, SCAN_T, 0, sc>>>(n);
    k_scan_offsets<<<1, 32, 0, sc>>>(nb);
    k_scan_final<<<nb, SCAN_T, 0, sc>>>(n, e);
    k_fill<<<(e + 255) / 256, 256, 0, sc>>>(row, col, e);

    if (fork) cudaEventRecord(ev_join, s2);

    // ---- GEMM1 (fp32 in, fp16 out) overlaps the CSR build ----
    k_gemm_mma<float><<<gemm_blocks, 256, GSMEM_FLOATS * 4>>>(x, W1, h, n);

    if (fork) cudaStreamWaitEvent((cudaStream_t)0, ev_join, 0);

    // layer 1 aggregate: z = relu(Ahat h + b1)   (fp16 out)
    k_agg<__half><<<agg_blocks, 256>>>(h, b1, z, n, 1);
    // layer 2: h = z @ W2 (fp16 in/out) ; out = Ahat h + b2 (fp32 out)
    k_gemm_mma<__half><<<gemm_blocks, 256, GSMEM_FLOATS * 4>>>(z, W2, h, n);
    k_agg<float><<<agg_blocks, 256>>>(h, b2, out, n, 0);
}